// round 2
// baseline (speedup 1.0000x reference)
#include <cuda_runtime.h>
#include <cuda_bf16.h>
#include <cstdint>

#define B_   128
#define S_   512
#define D_   2048
#define N_   128
#define NN_  16384
#define KT   32
#define SROW 40   /* bf16 elements per smem row: 32 + 8 pad -> 80B row stride */

// ---------------- scratch (device globals; no allocation) ----------------
__device__ __align__(16) float g_mean[B_ * D_];      // 1 MB
__device__ __align__(16) float g_ctx [B_ * D_];      // 1 MB
__device__ __align__(16) float g_warp[B_ * NN_];     // 8 MB
__device__ __align__(16) float g_part[128 * NN_];    // 8 MB split-K partials for raw

// ---------------- helpers ----------------
__device__ __forceinline__ uint32_t f2bf2(float lo, float hi) {
    uint32_t r;
    asm("cvt.rn.bf16x2.f32 %0, %1, %2;" : "=r"(r) : "f"(hi), "f"(lo));  // hi -> upper 16
    return r;
}
__device__ __forceinline__ void ldsm_x4(uint32_t* r, uint32_t a) {
    asm volatile("ldmatrix.sync.aligned.m8n8.x4.shared.b16 {%0,%1,%2,%3}, [%4];"
                 : "=r"(r[0]), "=r"(r[1]), "=r"(r[2]), "=r"(r[3]) : "r"(a));
}
__device__ __forceinline__ void ldsm_x2(uint32_t* r, uint32_t a) {
    asm volatile("ldmatrix.sync.aligned.m8n8.x2.shared.b16 {%0,%1}, [%2];"
                 : "=r"(r[0]), "=r"(r[1]) : "r"(a));
}
__device__ __forceinline__ void mma_bf16(float* c, const uint32_t* a, const uint32_t* b) {
    asm volatile(
        "mma.sync.aligned.m16n8k16.row.col.f32.bf16.bf16.f32 "
        "{%0,%1,%2,%3}, {%4,%5,%6,%7}, {%8,%9}, {%0,%1,%2,%3};"
        : "+f"(c[0]), "+f"(c[1]), "+f"(c[2]), "+f"(c[3])
        : "r"(a[0]), "r"(a[1]), "r"(a[2]), "r"(a[3]), "r"(b[0]), "r"(b[1]));
}

// ---------------- kernel 1: mean over sequence ----------------
// grid = B*8 (1024 blocks), block 64. Each thread owns one float4 column, 512 rows.
__global__ void k_mean(const float4* __restrict__ x4, float4* __restrict__ m4) {
    int b  = blockIdx.x >> 3;
    int d4 = ((blockIdx.x & 7) << 6) + threadIdx.x;     // 0..511
    const float4* p = x4 + (size_t)b * (S_ * D_ / 4) + d4;
    float4 acc[8];
    #pragma unroll
    for (int u = 0; u < 8; u++) acc[u] = make_float4(0.f, 0.f, 0.f, 0.f);
    for (int s = 0; s < S_; s += 8) {
        #pragma unroll
        for (int u = 0; u < 8; u++) {
            float4 v = __ldcs(&p[(size_t)(s + u) * (D_ / 4)]);
            acc[u].x += v.x; acc[u].y += v.y; acc[u].z += v.z; acc[u].w += v.w;
        }
    }
    #pragma unroll
    for (int u = 0; u < 4; u++) {
        acc[u].x += acc[u+4].x; acc[u].y += acc[u+4].y;
        acc[u].z += acc[u+4].z; acc[u].w += acc[u+4].w;
    }
    acc[0].x += acc[2].x; acc[0].y += acc[2].y; acc[0].z += acc[2].z; acc[0].w += acc[2].w;
    acc[1].x += acc[3].x; acc[1].y += acc[3].y; acc[1].z += acc[3].z; acc[1].w += acc[3].w;
    const float inv = 1.f / (float)S_;
    float4 m;
    m.x = (acc[0].x + acc[1].x) * inv;
    m.y = (acc[0].y + acc[1].y) * inv;
    m.z = (acc[0].z + acc[1].z) * inv;
    m.w = (acc[0].w + acc[1].w) * inv;
    m4[b * (D_ / 4) + d4] = m;
}

// ---------------- bf16-smem ldmatrix GEMM ----------------
// out[128, Nfull] = A[128,2048] @ Bm[Nfull,2048]^T  (per-block columns NT)
// EPI: 0 plain, 1 +bias, 2 (+bias)*0.1
// 256 threads = 8 warps as 4(M-groups of 32 rows) x 2(N-halves).
// smem tiles bf16, double-buffered; gmem loads staged in registers (2 deep).
template<int NT, int EPI>
__global__ void __launch_bounds__(256, 1)
k_gemm(const float* __restrict__ A, const float* __restrict__ Bm,
       const float* __restrict__ bias, float* __restrict__ out, int Nfull) {
    constexpr int ASZ = 128 * SROW;          // elements per A stage
    constexpr int BSZ = NT  * SROW;
    constexpr int NB  = NT / 32;             // B float4 loads per thread per stage
    constexpr int NLD = 4 + NB;
    constexpr int NJ  = NT / 16;             // n8 tiles per warp

    extern __shared__ __align__(16) __nv_bfloat16 sm[];
    __nv_bfloat16* As = sm;                  // [2][128][SROW]
    __nv_bfloat16* Bs = sm + 2 * ASZ;        // [2][NT ][SROW]
    const uint32_t smbase = (uint32_t)__cvta_generic_to_shared(sm);

    const int tid  = threadIdx.x;
    const int warp = tid >> 5, lane = tid & 31;
    const int wy   = warp >> 1, wx = warp & 1;
    const int row0 = wy * 32;
    const int n0   = blockIdx.x * NT;
    const int wxn0 = wx * (NT / 2);

    // fragment smem offsets (element units), per lane
    const int aLane = (lane & 15) * SROW + ((lane >> 4) & 1) * 8;
    const int bLane = (lane & 7)  * SROW + ((lane >> 3) & 1) * 8;

    float acc[2][NJ][4];
    #pragma unroll
    for (int m = 0; m < 2; m++)
        #pragma unroll
        for (int j = 0; j < NJ; j++)
            acc[m][j][0] = acc[m][j][1] = acc[m][j][2] = acc[m][j][3] = 0.f;

    float4 rb[2][NLD];

    auto ldg_tile = [&](float4* r, int k0) {
        #pragma unroll
        for (int u = 0; u < 4; u++) {                       // A: 128x32 fp32
            int i  = tid + u * 256;
            int rr = i >> 3, cc = (i & 7) * 4;
            r[u] = *(const float4*)&A[(size_t)rr * D_ + k0 + cc];
        }
        #pragma unroll
        for (int u = 0; u < NB; u++) {                      // B: NTx32 fp32
            int i  = tid + u * 256;
            int rr = i >> 3, cc = (i & 7) * 4;
            r[4 + u] = *(const float4*)&Bm[(size_t)(n0 + rr) * D_ + k0 + cc];
        }
    };
    auto sts_tile = [&](int st, const float4* r) {
        #pragma unroll
        for (int u = 0; u < 4; u++) {
            int i  = tid + u * 256;
            int rr = i >> 3, cc = (i & 7) * 4;
            uint2 pk = make_uint2(f2bf2(r[u].x, r[u].y), f2bf2(r[u].z, r[u].w));
            *(uint2*)&As[(size_t)st * ASZ + rr * SROW + cc] = pk;
        }
        #pragma unroll
        for (int u = 0; u < NB; u++) {
            int i  = tid + u * 256;
            int rr = i >> 3, cc = (i & 7) * 4;
            uint2 pk = make_uint2(f2bf2(r[4+u].x, r[4+u].y), f2bf2(r[4+u].z, r[4+u].w));
            *(uint2*)&Bs[(size_t)st * BSZ + rr * SROW + cc] = pk;
        }
    };
    auto compute = [&](int st) {
        const uint32_t aB = smbase + 2u * (st * ASZ + row0 * SROW + aLane);
        const uint32_t bB = smbase + 2u * (2 * ASZ + st * BSZ + wxn0 * SROW + bLane);
        #pragma unroll
        for (int h = 0; h < 2; h++) {
            uint32_t a[2][4];
            ldsm_x4(a[0], aB + 2u * (h * 16));
            ldsm_x4(a[1], aB + 2u * (16 * SROW + h * 16));
            #pragma unroll
            for (int j = 0; j < NJ; j++) {
                uint32_t b[2];
                ldsm_x2(b, bB + 2u * (j * 8 * SROW + h * 16));
                mma_bf16(acc[0][j], a[0], b);
                mma_bf16(acc[1][j], a[1], b);
            }
        }
    };

    constexpr int NK = D_ / KT;   // 64
    ldg_tile(rb[0], 0);
    sts_tile(0, rb[0]);
    ldg_tile(rb[1], KT);
    __syncthreads();

    for (int kt = 0; kt < NK; kt++) {
        int st = kt & 1;
        if (kt + 2 < NK) ldg_tile(rb[kt & 1], (kt + 2) * KT);
        if (kt + 1 < NK) sts_tile(st ^ 1, rb[(kt + 1) & 1]);
        compute(st);
        __syncthreads();
    }

    const int r_ = lane >> 2, c_ = lane & 3;
    #pragma unroll
    for (int m = 0; m < 2; m++) {
        #pragma unroll
        for (int j = 0; j < NJ; j++) {
            int row = row0 + m * 16 + r_;
            int col = n0 + wxn0 + j * 8 + 2 * c_;
            float bv0 = 0.f, bv1 = 0.f;
            if (EPI >= 1) { bv0 = bias[col]; bv1 = bias[col + 1]; }
            float o00 = acc[m][j][0] + bv0, o01 = acc[m][j][1] + bv1;
            float o10 = acc[m][j][2] + bv0, o11 = acc[m][j][3] + bv1;
            if (EPI == 2) { o00 *= 0.1f; o01 *= 0.1f; o10 *= 0.1f; o11 *= 0.1f; }
            out[(size_t)row       * Nfull + col    ] = o00;
            out[(size_t)row       * Nfull + col + 1] = o01;
            out[(size_t)(row + 8) * Nfull + col    ] = o10;
            out[(size_t)(row + 8) * Nfull + col + 1] = o11;
        }
    }
}

// ---------------- raw-score split-K partials (fp32, deterministic) ----------------
// grid 128 (K chunks of 16), block 256. part[ks][b][j] = sum_{k in chunk} ctx[b][k]*rs[j][k]
__global__ void k_rawpart(const float* __restrict__ ctx, const float* __restrict__ rs,
                          float* __restrict__ part) {
    __shared__ float cs [128][20];
    __shared__ float rss[128][20];
    const int tid = threadIdx.x;
    const int k0  = blockIdx.x * 16;
    #pragma unroll
    for (int u = 0; u < 2; u++) {
        int i  = tid + u * 256;
        int rr = i >> 2, cc = (i & 3) * 4;
        *(float4*)&cs [rr][cc] = *(const float4*)&ctx[(size_t)rr * D_ + k0 + cc];
        *(float4*)&rss[rr][cc] = *(const float4*)&rs [(size_t)rr * D_ + k0 + cc];
    }
    __syncthreads();
    const int bb = tid >> 4;   // 0..15
    const int jj = tid & 15;   // 0..15
    float a[8][8];
    #pragma unroll
    for (int u = 0; u < 8; u++)
        #pragma unroll
        for (int v = 0; v < 8; v++) a[u][v] = 0.f;
    #pragma unroll
    for (int k = 0; k < 16; k++) {
        float cv[8], rv[8];
        #pragma unroll
        for (int u = 0; u < 8; u++) { cv[u] = cs[bb + 16*u][k]; rv[u] = rss[jj + 16*u][k]; }
        #pragma unroll
        for (int u = 0; u < 8; u++)
            #pragma unroll
            for (int v = 0; v < 8; v++) a[u][v] += cv[u] * rv[v];
    }
    float* po = part + (size_t)blockIdx.x * NN_;
    #pragma unroll
    for (int u = 0; u < 8; u++)
        #pragma unroll
        for (int v = 0; v < 8; v++)
            po[(bb + 16*u) * N_ + (jj + 16*v)] = a[u][v];
}

// ---------------- final: reduce raw partials + softmax + warped scores + sigmoid ----------------
// grid 128 (b), block 128 (thread = row i).
__global__ void k_final(const float* __restrict__ adj, const float* __restrict__ warp_,
                        const float* __restrict__ part, float* __restrict__ out) {
    extern __shared__ float smf[];
    float (*s)[129] = reinterpret_cast<float(*)[129]>(smf);
    float* raws = smf + 128 * 129;
    const int b = blockIdx.x, t = threadIdx.x;

    float rsum = 0.f;
    #pragma unroll 8
    for (int ks = 0; ks < 128; ks++) rsum += part[(size_t)ks * NN_ + b * N_ + t];
    raws[t] = rsum;

    const float* wp = warp_ + (size_t)b * NN_;
    for (int idx = t; idx < NN_; idx += 128)
        s[idx >> 7][idx & 127] = adj[idx] + wp[idx];
    __syncthreads();

    float m = -1e30f;
    #pragma unroll 4
    for (int j = 0; j < N_; j++) m = fmaxf(m, s[t][j]);
    float sum = 0.f, dot = 0.f;
    #pragma unroll 4
    for (int j = 0; j < N_; j++) {
        float e = __expf(s[t][j] - m);
        sum += e;
        dot += e * raws[j];
    }
    float w = dot / sum;
    out[b * N_ + t] = 1.f / (1.f + __expf(-w));
}

// ---------------- launch ----------------
extern "C" void kernel_launch(void* const* d_in, const int* in_sizes, int n_in,
                              void* d_out, int out_size) {
    const float* x   = (const float*)d_in[0];   // [128,512,2048]
    const float* rs  = (const float*)d_in[1];   // [128,2048]
    const float* Wc  = (const float*)d_in[2];   // [2048,2048]
    const float* bc  = (const float*)d_in[3];   // [2048]
    const float* Ww  = (const float*)d_in[4];   // [16384,2048]
    const float* bw  = (const float*)d_in[5];   // [16384]
    const float* adj = (const float*)d_in[6];   // [128,128]
    float* out = (float*)d_out;

    float *p_mean, *p_ctx, *p_warp, *p_part;
    cudaGetSymbolAddress((void**)&p_mean, g_mean);
    cudaGetSymbolAddress((void**)&p_ctx,  g_ctx);
    cudaGetSymbolAddress((void**)&p_warp, g_warp);
    cudaGetSymbolAddress((void**)&p_part, g_part);

    // 1. mean over S  (HBM-bound, 512 MB)
    k_mean<<<B_ * 8, 64>>>((const float4*)x, (float4*)p_mean);

    // 2. context = mean @ Wc^T + bc   (bf16 ldmatrix GEMM, NT=32 -> 64 blocks)
    {
        size_t sh = (size_t)(2 * 128 * SROW + 2 * 32 * SROW) * sizeof(__nv_bfloat16);
        cudaFuncSetAttribute(k_gemm<32, 1>, cudaFuncAttributeMaxDynamicSharedMemorySize, (int)sh);
        k_gemm<32, 1><<<D_ / 32, 256, sh>>>(p_mean, Wc, bc, p_ctx, D_);
    }

    // 3. raw partials = ctx @ rs^T (fp32 split-K over 128 blocks)
    k_rawpart<<<128, 256>>>(p_ctx, rs, p_part);

    // 4. warp = 0.1*(ctx @ Ww^T + bw)  (bf16 ldmatrix GEMM, NT=128 -> 128 blocks)
    {
        size_t sh = (size_t)(2 * 128 * SROW + 2 * 128 * SROW) * sizeof(__nv_bfloat16);
        cudaFuncSetAttribute(k_gemm<128, 2>, cudaFuncAttributeMaxDynamicSharedMemorySize, (int)sh);
        k_gemm<128, 2><<<NN_ / 128, 256, sh>>>(p_ctx, Ww, bw, p_warp, NN_);
    }

    // 5. reduce raw + softmax(adj + warp) @ raw -> sigmoid
    {
        size_t sh = (size_t)(128 * 129 + 128) * sizeof(float);
        cudaFuncSetAttribute(k_final, cudaFuncAttributeMaxDynamicSharedMemorySize, (int)sh);
        k_final<<<B_, 128, sh>>>(adj, p_warp, p_part, out);
    }
}

// round 3
// speedup vs baseline: 1.4742x; 1.4742x over previous
#include <cuda_runtime.h>
#include <cuda_bf16.h>
#include <cstdint>

#define B_   128
#define S_   512
#define D_   2048
#define N_   128
#define NN_  16384
#define KT   32
#define PAD  40      /* fp32 words per smem row: 160B -> conflict-free frag loads */
#define STAGES 4

// ---------------- scratch (device globals; no allocation) ----------------
__device__ __align__(16) float g_mean[B_ * D_];      // 1 MB
__device__ __align__(16) float g_ctx [B_ * D_];      // 1 MB
__device__ __align__(16) float g_warp[B_ * NN_];     // 8 MB
__device__ __align__(16) float g_part[128 * NN_];    // 8 MB split-K partials for raw

// ---------------- helpers ----------------
__device__ __forceinline__ void cp_async16(void* smem, const void* gmem) {
    uint32_t s = (uint32_t)__cvta_generic_to_shared(smem);
    asm volatile("cp.async.cg.shared.global [%0], [%1], 16;\n" :: "r"(s), "l"(gmem));
}
__device__ __forceinline__ uint32_t f2bf2(float lo, float hi) {
    uint32_t r;
    asm("cvt.rn.bf16x2.f32 %0, %1, %2;" : "=r"(r) : "f"(hi), "f"(lo));  // hi -> upper 16
    return r;
}
__device__ __forceinline__ void mma_bf16(float* c, const uint32_t* a, const uint32_t* b) {
    asm volatile(
        "mma.sync.aligned.m16n8k16.row.col.f32.bf16.bf16.f32 "
        "{%0,%1,%2,%3}, {%4,%5,%6,%7}, {%8,%9}, {%0,%1,%2,%3};"
        : "+f"(c[0]), "+f"(c[1]), "+f"(c[2]), "+f"(c[3])
        : "r"(a[0]), "r"(a[1]), "r"(a[2]), "r"(a[3]), "r"(b[0]), "r"(b[1]));
}

// ---------------- kernel 1: mean over sequence ----------------
__global__ void k_mean(const float4* __restrict__ x4, float4* __restrict__ m4) {
    int b  = blockIdx.x >> 3;
    int d4 = ((blockIdx.x & 7) << 6) + threadIdx.x;     // 0..511
    const float4* p = x4 + (size_t)b * (S_ * D_ / 4) + d4;
    float4 acc[8];
    #pragma unroll
    for (int u = 0; u < 8; u++) acc[u] = make_float4(0.f, 0.f, 0.f, 0.f);
    for (int s = 0; s < S_; s += 8) {
        #pragma unroll
        for (int u = 0; u < 8; u++) {
            float4 v = __ldcs(&p[(size_t)(s + u) * (D_ / 4)]);
            acc[u].x += v.x; acc[u].y += v.y; acc[u].z += v.z; acc[u].w += v.w;
        }
    }
    #pragma unroll
    for (int u = 0; u < 4; u++) {
        acc[u].x += acc[u+4].x; acc[u].y += acc[u+4].y;
        acc[u].z += acc[u+4].z; acc[u].w += acc[u+4].w;
    }
    acc[0].x += acc[2].x; acc[0].y += acc[2].y; acc[0].z += acc[2].z; acc[0].w += acc[2].w;
    acc[1].x += acc[3].x; acc[1].y += acc[3].y; acc[1].z += acc[3].z; acc[1].w += acc[3].w;
    const float inv = 1.f / (float)S_;
    float4 m;
    m.x = (acc[0].x + acc[1].x) * inv;
    m.y = (acc[0].y + acc[1].y) * inv;
    m.z = (acc[0].z + acc[1].z) * inv;
    m.w = (acc[0].w + acc[1].w) * inv;
    m4[b * (D_ / 4) + d4] = m;
}

// ---------------- cp.async 4-stage GEMM ----------------
// out[128, Nfull] = A[128,2048] @ Bm[Nfull,2048]^T, NT cols per block.
// EPI: 1 = +bias, 2 = (+bias)*0.1
// 256 threads = 8 warps laid out 4(M: 32-row groups) x 2(N: NT/2 halves).
// fp32 smem tiles (STAGES deep), fragments via LDS.64 + cvt.bf16x2, mma bf16.
template<int NT, int EPI>
__global__ void __launch_bounds__(256, 1)
k_gemm(const float* __restrict__ A, const float* __restrict__ Bm,
       const float* __restrict__ bias, float* __restrict__ out, int Nfull) {
    constexpr int ASZ = 128 * PAD;           // floats per A stage
    constexpr int BSZ = NT  * PAD;
    constexpr int NB  = NT / 32;             // B cp.async ops per thread per stage
    constexpr int NJ  = (NT / 2) / 8;        // n8 tiles per warp

    extern __shared__ __align__(16) float sm[];
    float* As = sm;                          // [STAGES][128][PAD]
    float* Bs = sm + STAGES * ASZ;           // [STAGES][NT ][PAD]

    const int tid  = threadIdx.x;
    const int warp = tid >> 5, lane = tid & 31;
    const int wy   = warp >> 1, wx = warp & 1;
    const int row0 = wy * 32;
    const int n0   = blockIdx.x * NT;
    const int wxn0 = wx * (NT / 2);
    const int r    = lane >> 2, c = lane & 3;

    float acc[2][NJ][4];
    #pragma unroll
    for (int m = 0; m < 2; m++)
        #pragma unroll
        for (int j = 0; j < NJ; j++)
            acc[m][j][0] = acc[m][j][1] = acc[m][j][2] = acc[m][j][3] = 0.f;

    auto issue = [&](int kt) {
        int st = kt & (STAGES - 1);
        int k0 = kt * KT;
        #pragma unroll
        for (int u = 0; u < 4; u++) {                       // A: 128x32 fp32
            int i  = tid + u * 256;
            int rr = i >> 3, cc = (i & 7) * 4;
            cp_async16(&As[st * ASZ + rr * PAD + cc], &A[(size_t)rr * D_ + k0 + cc]);
        }
        #pragma unroll
        for (int u = 0; u < NB; u++) {                      // B: NTx32 fp32
            int i  = tid + u * 256;
            int rr = i >> 3, cc = (i & 7) * 4;
            cp_async16(&Bs[st * BSZ + rr * PAD + cc], &Bm[(size_t)(n0 + rr) * D_ + k0 + cc]);
        }
    };

    constexpr int NK = D_ / KT;   // 64
    #pragma unroll
    for (int s = 0; s < STAGES - 1; s++) {
        issue(s);
        asm volatile("cp.async.commit_group;\n");
    }

    for (int kt = 0; kt < NK; kt++) {
        int st = kt & (STAGES - 1);
        asm volatile("cp.async.wait_group %0;\n" :: "n"(STAGES - 2));
        __syncthreads();
        if (kt + STAGES - 1 < NK) issue(kt + STAGES - 1);
        asm volatile("cp.async.commit_group;\n");

        const float* Ast = As + st * ASZ;
        const float* Bst = Bs + st * BSZ;
        #pragma unroll
        for (int h = 0; h < 2; h++) {
            const int kb = h * 16 + 2 * c;
            uint32_t a[2][4];
            #pragma unroll
            for (int m = 0; m < 2; m++) {
                const float* ap = Ast + (row0 + m * 16 + r) * PAD + kb;
                float2 v;
                v = *(const float2*)(ap);                 a[m][0] = f2bf2(v.x, v.y);
                v = *(const float2*)(ap + 8 * PAD);       a[m][1] = f2bf2(v.x, v.y);
                v = *(const float2*)(ap + 8);             a[m][2] = f2bf2(v.x, v.y);
                v = *(const float2*)(ap + 8 * PAD + 8);   a[m][3] = f2bf2(v.x, v.y);
            }
            #pragma unroll
            for (int j = 0; j < NJ; j++) {
                const float* bp = Bst + (wxn0 + j * 8 + r) * PAD + kb;
                float2 v;
                uint32_t b[2];
                v = *(const float2*)(bp);       b[0] = f2bf2(v.x, v.y);
                v = *(const float2*)(bp + 8);   b[1] = f2bf2(v.x, v.y);
                mma_bf16(acc[0][j], a[0], b);
                mma_bf16(acc[1][j], a[1], b);
            }
        }
    }

    #pragma unroll
    for (int m = 0; m < 2; m++) {
        #pragma unroll
        for (int j = 0; j < NJ; j++) {
            int row = row0 + m * 16 + r;
            int col = n0 + wxn0 + j * 8 + 2 * c;
            float bv0 = bias[col], bv1 = bias[col + 1];
            float o00 = acc[m][j][0] + bv0, o01 = acc[m][j][1] + bv1;
            float o10 = acc[m][j][2] + bv0, o11 = acc[m][j][3] + bv1;
            if (EPI == 2) { o00 *= 0.1f; o01 *= 0.1f; o10 *= 0.1f; o11 *= 0.1f; }
            out[(size_t)row       * Nfull + col    ] = o00;
            out[(size_t)row       * Nfull + col + 1] = o01;
            out[(size_t)(row + 8) * Nfull + col    ] = o10;
            out[(size_t)(row + 8) * Nfull + col + 1] = o11;
        }
    }
}

// ---------------- raw-score split-K partials (fp32, deterministic) ----------------
__global__ void k_rawpart(const float* __restrict__ ctx, const float* __restrict__ rs,
                          float* __restrict__ part) {
    __shared__ float cs [128][20];
    __shared__ float rss[128][20];
    const int tid = threadIdx.x;
    const int k0  = blockIdx.x * 16;
    #pragma unroll
    for (int u = 0; u < 2; u++) {
        int i  = tid + u * 256;
        int rr = i >> 2, cc = (i & 3) * 4;
        *(float4*)&cs [rr][cc] = *(const float4*)&ctx[(size_t)rr * D_ + k0 + cc];
        *(float4*)&rss[rr][cc] = *(const float4*)&rs [(size_t)rr * D_ + k0 + cc];
    }
    __syncthreads();
    const int bb = tid >> 4;
    const int jj = tid & 15;
    float a[8][8];
    #pragma unroll
    for (int u = 0; u < 8; u++)
        #pragma unroll
        for (int v = 0; v < 8; v++) a[u][v] = 0.f;
    #pragma unroll
    for (int k = 0; k < 16; k++) {
        float cv[8], rv[8];
        #pragma unroll
        for (int u = 0; u < 8; u++) { cv[u] = cs[bb + 16*u][k]; rv[u] = rss[jj + 16*u][k]; }
        #pragma unroll
        for (int u = 0; u < 8; u++)
            #pragma unroll
            for (int v = 0; v < 8; v++) a[u][v] += cv[u] * rv[v];
    }
    float* po = part + (size_t)blockIdx.x * NN_;
    #pragma unroll
    for (int u = 0; u < 8; u++)
        #pragma unroll
        for (int v = 0; v < 8; v++)
            po[(bb + 16*u) * N_ + (jj + 16*v)] = a[u][v];
}

// ---------------- final: reduce raw partials + softmax + warped scores + sigmoid ----------------
__global__ void k_final(const float* __restrict__ adj, const float* __restrict__ warp_,
                        const float* __restrict__ part, float* __restrict__ out) {
    extern __shared__ float smf[];
    float (*s)[129] = reinterpret_cast<float(*)[129]>(smf);
    float* raws = smf + 128 * 129;
    const int b = blockIdx.x, t = threadIdx.x;

    float rsum = 0.f;
    #pragma unroll 8
    for (int ks = 0; ks < 128; ks++) rsum += part[(size_t)ks * NN_ + b * N_ + t];
    raws[t] = rsum;

    const float* wp = warp_ + (size_t)b * NN_;
    for (int idx = t; idx < NN_; idx += 128)
        s[idx >> 7][idx & 127] = adj[idx] + wp[idx];
    __syncthreads();

    float m = -1e30f;
    #pragma unroll 4
    for (int j = 0; j < N_; j++) m = fmaxf(m, s[t][j]);
    float sum = 0.f, dot = 0.f;
    #pragma unroll 4
    for (int j = 0; j < N_; j++) {
        float e = __expf(s[t][j] - m);
        sum += e;
        dot += e * raws[j];
    }
    float w = dot / sum;
    out[b * N_ + t] = 1.f / (1.f + __expf(-w));
}

// ---------------- launch ----------------
extern "C" void kernel_launch(void* const* d_in, const int* in_sizes, int n_in,
                              void* d_out, int out_size) {
    const float* x   = (const float*)d_in[0];
    const float* rs  = (const float*)d_in[1];
    const float* Wc  = (const float*)d_in[2];
    const float* bc  = (const float*)d_in[3];
    const float* Ww  = (const float*)d_in[4];
    const float* bw  = (const float*)d_in[5];
    const float* adj = (const float*)d_in[6];
    float* out = (float*)d_out;

    float *p_mean, *p_ctx, *p_warp, *p_part;
    cudaGetSymbolAddress((void**)&p_mean, g_mean);
    cudaGetSymbolAddress((void**)&p_ctx,  g_ctx);
    cudaGetSymbolAddress((void**)&p_warp, g_warp);
    cudaGetSymbolAddress((void**)&p_part, g_part);

    // 1. mean over S  (HBM-bound, 512 MB)
    k_mean<<<B_ * 8, 64>>>((const float4*)x, (float4*)p_mean);

    // 2. context = mean @ Wc^T + bc
    {
        size_t sh = (size_t)(STAGES * 128 * PAD + STAGES * 32 * PAD) * sizeof(float);
        cudaFuncSetAttribute(k_gemm<32, 1>, cudaFuncAttributeMaxDynamicSharedMemorySize, (int)sh);
        k_gemm<32, 1><<<D_ / 32, 256, sh>>>(p_mean, Wc, bc, p_ctx, D_);
    }

    // 3. raw partials = ctx @ rs^T
    k_rawpart<<<128, 256>>>(p_ctx, rs, p_part);

    // 4. warp = 0.1*(ctx @ Ww^T + bw)
    {
        size_t sh = (size_t)(STAGES * 128 * PAD + STAGES * 128 * PAD) * sizeof(float);
        cudaFuncSetAttribute(k_gemm<128, 2>, cudaFuncAttributeMaxDynamicSharedMemorySize, (int)sh);
        k_gemm<128, 2><<<NN_ / 128, 256, sh>>>(p_ctx, Ww, bw, p_warp, NN_);
    }

    // 5. reduce raw + softmax(adj + warp) @ raw -> sigmoid
    {
        size_t sh = (size_t)(128 * 129 + 128) * sizeof(float);
        cudaFuncSetAttribute(k_final, cudaFuncAttributeMaxDynamicSharedMemorySize, (int)sh);
        k_final<<<B_, 128, sh>>>(adj, p_warp, p_part, out);
    }
}